// round 2
// baseline (speedup 1.0000x reference)
#include <cuda_runtime.h>

// input  [4,10,5,384,384] f32, target [4,10,1,384,384] f32, weight [5] f32
#define HW4    36864                 // (384*384)/4 float4 items per plane
#define NT     40                    // 4*10
#define XB     24                    // x-blocks per plane
#define NTHR   256
#define ITERS  (HW4 / (XB * NTHR))   // = 6, exact
#define NBLKS  (XB * NT)             // 960

// Scratch (zero-initialized at module load; finalizer re-zeros after each use
// so every kernel_launch call sees the same initial state -> deterministic).
// [0..4] sumx, [5..8] A_k = sum x_k*p_k, [9..12] B_k = sum x_{k+1}*p_k, [13..16] c_k
__device__ double   g_acc[17];
__device__ unsigned g_count;

typedef unsigned long long u64;

__device__ __forceinline__ u64 pack2(float lo, float hi) {
    u64 r; asm("mov.b64 %0, {%1, %2};" : "=l"(r) : "f"(lo), "f"(hi)); return r;
}
__device__ __forceinline__ void fma2(u64& acc, u64 a, u64 b) {
    asm("fma.rn.f32x2 %0, %1, %2, %0;" : "+l"(acc) : "l"(a), "l"(b));
}
__device__ __forceinline__ void add2(u64& acc, u64 a) {
    asm("add.rn.f32x2 %0, %0, %1;" : "+l"(acc) : "l"(a));
}
// 1.0f if a >= b else 0.0f (single FSET, no branch)
__device__ __forceinline__ float fset_ge(float a, float b) {
    float d; asm("set.ge.f32.f32 %0, %1, %2;" : "=f"(d) : "f"(a), "f"(b)); return d;
}
__device__ __forceinline__ float upsum(u64 v) {
    float lo, hi; asm("mov.b64 {%0, %1}, %2;" : "=f"(lo), "=f"(hi) : "l"(v));
    return lo + hi;
}

__global__ void __launch_bounds__(NTHR) dice_fused(
    const float4* __restrict__ x, const float4* __restrict__ t,
    const float* __restrict__ w, float* __restrict__ out, double npos)
{
    u64 s0=0, s1=0, s2=0, s3=0, s4=0;          // packed f32x2 accumulators
    u64 A0=0, A1=0, A2=0, A3=0;
    u64 B0=0, B1=0, B2=0, B3=0;
    u64 C0=0, C1=0, C2=0, C3=0;

    const int nt = blockIdx.y;
    const float4* __restrict__ xb = x + (size_t)nt * (5 * HW4);
    const float4* __restrict__ tb = t + (size_t)nt * HW4;

    int i = blockIdx.x * NTHR + threadIdx.x;
#pragma unroll
    for (int it = 0; it < ITERS; ++it, i += XB * NTHR) {
        const float4 x0 = xb[0 * HW4 + i];
        const float4 x1 = xb[1 * HW4 + i];
        const float4 x2 = xb[2 * HW4 + i];
        const float4 x3 = xb[3 * HW4 + i];
        const float4 x4 = xb[4 * HW4 + i];
        const float4 tv = tb[i];

        const u64 x0l = pack2(x0.x, x0.y), x0h = pack2(x0.z, x0.w);
        const u64 x1l = pack2(x1.x, x1.y), x1h = pack2(x1.z, x1.w);
        const u64 x2l = pack2(x2.x, x2.y), x2h = pack2(x2.z, x2.w);
        const u64 x3l = pack2(x3.x, x3.y), x3h = pack2(x3.z, x3.w);
        const u64 x4l = pack2(x4.x, x4.y), x4h = pack2(x4.z, x4.w);

        add2(s0, x0l); add2(s0, x0h);
        add2(s1, x1l); add2(s1, x1h);
        add2(s2, x2l); add2(s2, x2h);
        add2(s3, x3l); add2(s3, x3h);
        add2(s4, x4l); add2(s4, x4h);

#define THR(thrv, xal, xah, xbl, xbh, Ck, Ak, Bk)                          \
        {                                                                  \
            const u64 ml = pack2(fset_ge(tv.x, thrv), fset_ge(tv.y, thrv));\
            const u64 mh = pack2(fset_ge(tv.z, thrv), fset_ge(tv.w, thrv));\
            add2(Ck, ml); add2(Ck, mh);                                    \
            fma2(Ak, xal, ml); fma2(Ak, xah, mh);                          \
            fma2(Bk, xbl, ml); fma2(Bk, xbh, mh);                          \
        }
        THR(0.25f,  x0l, x0h, x1l, x1h, C0, A0, B0)
        THR(0.375f, x1l, x1h, x2l, x2h, C1, A1, B1)
        THR(0.5f,   x2l, x2h, x3l, x3h, C2, A2, B2)
        THR(0.625f, x3l, x3h, x4l, x4h, C3, A3, B3)
#undef THR
    }

    // ---- block reduction: warp shuffle -> shared -> global double atomics ----
    float vals[17] = { upsum(s0), upsum(s1), upsum(s2), upsum(s3), upsum(s4),
                       upsum(A0), upsum(A1), upsum(A2), upsum(A3),
                       upsum(B0), upsum(B1), upsum(B2), upsum(B3),
                       upsum(C0), upsum(C1), upsum(C2), upsum(C3) };
#pragma unroll
    for (int k = 0; k < 17; k++) {
#pragma unroll
        for (int o = 16; o > 0; o >>= 1)
            vals[k] += __shfl_down_sync(0xFFFFFFFFu, vals[k], o);
    }

    __shared__ float s_acc[17];
    if (threadIdx.x < 17) s_acc[threadIdx.x] = 0.f;
    __syncthreads();
    if ((threadIdx.x & 31) == 0) {
#pragma unroll
        for (int k = 0; k < 17; k++) atomicAdd(&s_acc[k], vals[k]);
    }
    __syncthreads();
    if (threadIdx.x < 17)
        atomicAdd(&g_acc[threadIdx.x], (double)s_acc[threadIdx.x]);
    __syncthreads();

    // ---- last-block finalize (fused; no extra kernel launches) ----
    if (threadIdx.x == 0) {
        __threadfence();
        const unsigned done = atomicAdd(&g_count, 1u);
        if (done == NBLKS - 1) {
            double v[17];
#pragma unroll
            for (int k = 0; k < 17; k++) v[k] = atomicAdd(&g_acc[k], 0.0);

            double cnt[5], inter[5];
            cnt[0] = npos - v[13];
            cnt[1] = v[13] - v[14];
            cnt[2] = v[14] - v[15];
            cnt[3] = v[15] - v[16];
            cnt[4] = v[16];
            inter[0] = v[0] - v[5];
            inter[1] = v[9] - v[6];
            inter[2] = v[10] - v[7];
            inter[3] = v[11] - v[8];
            inter[4] = v[12];

            const double S = 1e-5;
            double loss = 0.0;
#pragma unroll
            for (int c = 0; c < 5; c++) {
                const double dice = 1.0 - (2.0 * inter[c] + S) / (v[c] + cnt[c] + S);
                loss += (double)w[c] * dice;
            }
            out[0] = (float)loss;

            // restore state for the next (graph-replayed) call
#pragma unroll
            for (int k = 0; k < 17; k++) g_acc[k] = 0.0;
            __threadfence();
            g_count = 0;
        }
    }
}

extern "C" void kernel_launch(void* const* d_in, const int* in_sizes, int n_in,
                              void* d_out, int out_size)
{
    const float4* x = (const float4*)d_in[0];
    const float4* t = (const float4*)d_in[1];
    const float*  w = (const float*)d_in[2];
    float* out = (float*)d_out;

    dim3 grid(XB, NT);
    dice_fused<<<grid, NTHR>>>(x, t, w, out, (double)in_sizes[1]);
}

// round 3
// speedup vs baseline: 1.1714x; 1.1714x over previous
#include <cuda_runtime.h>

// input  [4,10,5,384,384] f32, target [4,10,1,384,384] f32, weight [5] f32
#define HW4    36864                 // (384*384)/4 float4 items per plane
#define NT     40                    // 4*10
#define XB     24                    // x-blocks per plane
#define NTHR   256
#define ITERS  (HW4 / (XB * NTHR))   // = 6, exact
#define NBLKS  (XB * NT)             // 960

// Scratch (zero-init at module load; finalizer re-zeros after each use so
// every kernel_launch/graph-replay sees identical initial state).
// [0..4] sumx, [5..8] A_k = sum x_k*p_k, [9..12] B_k = sum x_{k+1}*p_k, [13..16] c_k
__device__ double   g_acc[17];
__device__ unsigned g_count;

__global__ void __launch_bounds__(NTHR, 5) dice_fused(
    const float4* __restrict__ x, const float4* __restrict__ t,
    const float* __restrict__ w, float* __restrict__ out, double npos)
{
    float s0 = 0.f, s1 = 0.f, s2 = 0.f, s3 = 0.f, s4 = 0.f;
    float A0 = 0.f, A1 = 0.f, A2 = 0.f, A3 = 0.f;
    float B0 = 0.f, B1 = 0.f, B2 = 0.f, B3 = 0.f;
    int   c0 = 0, c1 = 0, c2 = 0, c3 = 0;

    const int nt = blockIdx.y;
    const float4* __restrict__ xb = x + (size_t)nt * (5 * HW4);
    const float4* __restrict__ tb = t + (size_t)nt * HW4;

    int i = blockIdx.x * NTHR + threadIdx.x;
#pragma unroll
    for (int it = 0; it < ITERS; ++it, i += XB * NTHR) {
        const float4 x0 = xb[0 * HW4 + i];
        const float4 x1 = xb[1 * HW4 + i];
        const float4 x2 = xb[2 * HW4 + i];
        const float4 x3 = xb[3 * HW4 + i];
        const float4 x4 = xb[4 * HW4 + i];
        const float4 tv = tb[i];

        s0 += (x0.x + x0.y) + (x0.z + x0.w);
        s1 += (x1.x + x1.y) + (x1.z + x1.w);
        s2 += (x2.x + x2.y) + (x2.z + x2.w);
        s3 += (x3.x + x3.y) + (x3.z + x3.w);
        s4 += (x4.x + x4.y) + (x4.z + x4.w);

#define LANE(tj, a0, a1, a2, a3, a4)                                  \
        {                                                             \
            const bool p0 = (tj) >= 0.25f;                            \
            const bool p1 = (tj) >= 0.375f;                           \
            const bool p2 = (tj) >= 0.5f;                             \
            const bool p3 = (tj) >= 0.625f;                           \
            c0 += p0; c1 += p1; c2 += p2; c3 += p3;                   \
            if (p0) { A0 += (a0); B0 += (a1); }                       \
            if (p1) { A1 += (a1); B1 += (a2); }                       \
            if (p2) { A2 += (a2); B2 += (a3); }                       \
            if (p3) { A3 += (a3); B3 += (a4); }                       \
        }

        LANE(tv.x, x0.x, x1.x, x2.x, x3.x, x4.x);
        LANE(tv.y, x0.y, x1.y, x2.y, x3.y, x4.y);
        LANE(tv.z, x0.z, x1.z, x2.z, x3.z, x4.z);
        LANE(tv.w, x0.w, x1.w, x2.w, x3.w, x4.w);
#undef LANE
    }

    // ---- block reduction: warp shuffle -> shared -> global double atomics ----
    float vals[17] = { s0, s1, s2, s3, s4,
                       A0, A1, A2, A3,
                       B0, B1, B2, B3,
                       (float)c0, (float)c1, (float)c2, (float)c3 };
#pragma unroll
    for (int k = 0; k < 17; k++) {
#pragma unroll
        for (int o = 16; o > 0; o >>= 1)
            vals[k] += __shfl_down_sync(0xFFFFFFFFu, vals[k], o);
    }

    __shared__ float s_acc[17];
    if (threadIdx.x < 17) s_acc[threadIdx.x] = 0.f;
    __syncthreads();
    if ((threadIdx.x & 31) == 0) {
#pragma unroll
        for (int k = 0; k < 17; k++) atomicAdd(&s_acc[k], vals[k]);
    }
    __syncthreads();
    if (threadIdx.x < 17)
        atomicAdd(&g_acc[threadIdx.x], (double)s_acc[threadIdx.x]);
    __syncthreads();

    // ---- last-block finalize (fused; no extra kernel launches) ----
    if (threadIdx.x == 0) {
        __threadfence();
        const unsigned done = atomicAdd(&g_count, 1u);
        if (done == NBLKS - 1) {
            double v[17];
#pragma unroll
            for (int k = 0; k < 17; k++) v[k] = atomicAdd(&g_acc[k], 0.0);

            double cnt[5], inter[5];
            cnt[0] = npos - v[13];
            cnt[1] = v[13] - v[14];
            cnt[2] = v[14] - v[15];
            cnt[3] = v[15] - v[16];
            cnt[4] = v[16];
            inter[0] = v[0] - v[5];
            inter[1] = v[9] - v[6];
            inter[2] = v[10] - v[7];
            inter[3] = v[11] - v[8];
            inter[4] = v[12];

            const double S = 1e-5;
            double loss = 0.0;
#pragma unroll
            for (int c = 0; c < 5; c++) {
                const double dice = 1.0 - (2.0 * inter[c] + S) / (v[c] + cnt[c] + S);
                loss += (double)w[c] * dice;
            }
            out[0] = (float)loss;

            // restore state for the next (graph-replayed) call
#pragma unroll
            for (int k = 0; k < 17; k++) g_acc[k] = 0.0;
            __threadfence();
            g_count = 0;
        }
    }
}

extern "C" void kernel_launch(void* const* d_in, const int* in_sizes, int n_in,
                              void* d_out, int out_size)
{
    const float4* x = (const float4*)d_in[0];
    const float4* t = (const float4*)d_in[1];
    const float*  w = (const float*)d_in[2];
    float* out = (float*)d_out;

    dim3 grid(XB, NT);
    dice_fused<<<grid, NTHR>>>(x, t, w, out, (double)in_sizes[1]);
}

// round 4
// speedup vs baseline: 1.3031x; 1.1125x over previous
#include <cuda_runtime.h>

// input  [4,10,5,384,384] f32, target [4,10,1,384,384] f32, weight [5] f32
#define HW4    36864                 // (384*384)/4 float4 items per plane
#define NT     40                    // 4*10
#define XB     18                    // x-blocks per plane  -> 720 blocks total
#define NTHR   256
#define ITERS  (HW4 / (XB * NTHR))   // = 8, exact
#define NBLKS  (XB * NT)             // 720  (<= 148 SMs * 5 CTAs -> ONE wave)

// Scratch (zero-init at module load; finalizer re-zeros after each use so
// every kernel_launch/graph-replay sees identical initial state).
// [0..4] sumx, [5..8] A_k = sum x_k*p_k, [9..12] B_k = sum x_{k+1}*p_k, [13..16] c_k
__device__ double   g_acc[17];
__device__ unsigned g_count;

__global__ void __launch_bounds__(NTHR, 5) dice_fused(
    const float4* __restrict__ x, const float4* __restrict__ t,
    const float* __restrict__ w, float* __restrict__ out, double npos)
{
    float s0 = 0.f, s1 = 0.f, s2 = 0.f, s3 = 0.f, s4 = 0.f;
    float A0 = 0.f, A1 = 0.f, A2 = 0.f, A3 = 0.f;
    float B0 = 0.f, B1 = 0.f, B2 = 0.f, B3 = 0.f;
    // 4 threshold counters packed into 8-bit fields (max 4*ITERS = 32 < 256 each)
    unsigned cpk = 0;

    const int nt = blockIdx.y;
    const float4* __restrict__ xb = x + (size_t)nt * (5 * HW4);
    const float4* __restrict__ tb = t + (size_t)nt * HW4;

    int i = blockIdx.x * NTHR + threadIdx.x;
#pragma unroll
    for (int it = 0; it < ITERS; ++it, i += XB * NTHR) {
        const float4 x0 = xb[0 * HW4 + i];
        const float4 x1 = xb[1 * HW4 + i];
        const float4 x2 = xb[2 * HW4 + i];
        const float4 x3 = xb[3 * HW4 + i];
        const float4 x4 = xb[4 * HW4 + i];
        const float4 tv = tb[i];

        s0 += (x0.x + x0.y) + (x0.z + x0.w);
        s1 += (x1.x + x1.y) + (x1.z + x1.w);
        s2 += (x2.x + x2.y) + (x2.z + x2.w);
        s3 += (x3.x + x3.y) + (x3.z + x3.w);
        s4 += (x4.x + x4.y) + (x4.z + x4.w);

#define LANE(tj, a0, a1, a2, a3, a4)                                   \
        {                                                              \
            const bool p0 = (tj) >= 0.25f;                             \
            const bool p1 = (tj) >= 0.375f;                            \
            const bool p2 = (tj) >= 0.5f;                              \
            const bool p3 = (tj) >= 0.625f;                            \
            cpk += (unsigned)p0 | ((unsigned)p1 << 8)                  \
                 | ((unsigned)p2 << 16) | ((unsigned)p3 << 24);        \
            if (p0) { A0 += (a0); B0 += (a1); }                        \
            if (p1) { A1 += (a1); B1 += (a2); }                        \
            if (p2) { A2 += (a2); B2 += (a3); }                        \
            if (p3) { A3 += (a3); B3 += (a4); }                        \
        }

        LANE(tv.x, x0.x, x1.x, x2.x, x3.x, x4.x);
        LANE(tv.y, x0.y, x1.y, x2.y, x3.y, x4.y);
        LANE(tv.z, x0.z, x1.z, x2.z, x3.z, x4.z);
        LANE(tv.w, x0.w, x1.w, x2.w, x3.w, x4.w);
#undef LANE
    }

    // ---- block reduction: warp shuffle -> shared -> global double atomics ----
    float vals[17] = { s0, s1, s2, s3, s4,
                       A0, A1, A2, A3,
                       B0, B1, B2, B3,
                       (float)( cpk        & 0xFF),
                       (float)((cpk >> 8)  & 0xFF),
                       (float)((cpk >> 16) & 0xFF),
                       (float)((cpk >> 24) & 0xFF) };
#pragma unroll
    for (int k = 0; k < 17; k++) {
#pragma unroll
        for (int o = 16; o > 0; o >>= 1)
            vals[k] += __shfl_down_sync(0xFFFFFFFFu, vals[k], o);
    }

    __shared__ float s_acc[17];
    if (threadIdx.x < 17) s_acc[threadIdx.x] = 0.f;
    __syncthreads();
    if ((threadIdx.x & 31) == 0) {
#pragma unroll
        for (int k = 0; k < 17; k++) atomicAdd(&s_acc[k], vals[k]);
    }
    __syncthreads();
    if (threadIdx.x < 17)
        atomicAdd(&g_acc[threadIdx.x], (double)s_acc[threadIdx.x]);
    __syncthreads();

    // ---- last-block finalize (fused; no extra kernel launches) ----
    if (threadIdx.x == 0) {
        __threadfence();
        const unsigned done = atomicAdd(&g_count, 1u);
        if (done == NBLKS - 1) {
            double v[17];
#pragma unroll
            for (int k = 0; k < 17; k++) v[k] = atomicAdd(&g_acc[k], 0.0);

            double cnt[5], inter[5];
            cnt[0] = npos - v[13];
            cnt[1] = v[13] - v[14];
            cnt[2] = v[14] - v[15];
            cnt[3] = v[15] - v[16];
            cnt[4] = v[16];
            inter[0] = v[0] - v[5];
            inter[1] = v[9] - v[6];
            inter[2] = v[10] - v[7];
            inter[3] = v[11] - v[8];
            inter[4] = v[12];

            const double S = 1e-5;
            double loss = 0.0;
#pragma unroll
            for (int c = 0; c < 5; c++) {
                const double dice = 1.0 - (2.0 * inter[c] + S) / (v[c] + cnt[c] + S);
                loss += (double)w[c] * dice;
            }
            out[0] = (float)loss;

            // restore state for the next (graph-replayed) call
#pragma unroll
            for (int k = 0; k < 17; k++) g_acc[k] = 0.0;
            __threadfence();
            g_count = 0;
        }
    }
}

extern "C" void kernel_launch(void* const* d_in, const int* in_sizes, int n_in,
                              void* d_out, int out_size)
{
    const float4* x = (const float4*)d_in[0];
    const float4* t = (const float4*)d_in[1];
    const float*  w = (const float*)d_in[2];
    float* out = (float*)d_out;

    dim3 grid(XB, NT);
    dice_fused<<<grid, NTHR>>>(x, t, w, out, (double)in_sizes[1]);
}

// round 5
// speedup vs baseline: 1.3157x; 1.0096x over previous
#include <cuda_runtime.h>

// input  [4,10,5,384,384] f32, target [4,10,1,384,384] f32, weight [5] f32
#define HW4    36864                 // (384*384)/4 float4 items per plane
#define NT     40                    // 4*10
#define XB     18                    // x-blocks per plane  -> 720 blocks total
#define NTHR   256
#define ITERS  (HW4 / (XB * NTHR))   // = 8, exact
#define NBLKS  (XB * NT)             // 720  (<= 148 SMs * 5 CTAs -> ONE wave)

// Scratch (zero-init at module load; finalizer re-zeros after each use so
// every kernel_launch/graph-replay sees identical initial state).
// [0..4] sumx, [5..8] A_k = sum x_k*p_k, [9..12] B_k = sum x_{k+1}*p_k, [13..16] c_k
__device__ double   g_acc[17];
__device__ unsigned g_count;

__global__ void __launch_bounds__(NTHR, 5) dice_fused(
    const float4* __restrict__ x, const float4* __restrict__ t,
    const float* __restrict__ w, float* __restrict__ out, double npos)
{
    float s0 = 0.f, s1 = 0.f, s2 = 0.f, s3 = 0.f, s4 = 0.f;
    float A0 = 0.f, A1 = 0.f, A2 = 0.f, A3 = 0.f;
    float B0 = 0.f, B1 = 0.f, B2 = 0.f, B3 = 0.f;
    // 4 threshold counters packed into 8-bit fields (max 4*ITERS = 32 < 256 each)
    unsigned cpk = 0;

    const int nt = blockIdx.y;
    const float4* __restrict__ xb = x + (size_t)nt * (5 * HW4);
    const float4* __restrict__ tb = t + (size_t)nt * HW4;

    int i = blockIdx.x * NTHR + threadIdx.x;
#pragma unroll
    for (int it = 0; it < ITERS; ++it, i += XB * NTHR) {
        const float4 x0 = xb[0 * HW4 + i];
        const float4 x1 = xb[1 * HW4 + i];
        const float4 x2 = xb[2 * HW4 + i];
        const float4 x3 = xb[3 * HW4 + i];
        const float4 x4 = xb[4 * HW4 + i];
        const float4 tv = tb[i];

        s0 += (x0.x + x0.y) + (x0.z + x0.w);
        s1 += (x1.x + x1.y) + (x1.z + x1.w);
        s2 += (x2.x + x2.y) + (x2.z + x2.w);
        s3 += (x3.x + x3.y) + (x3.z + x3.w);
        s4 += (x4.x + x4.y) + (x4.z + x4.w);

#define LANE(tj, a0, a1, a2, a3, a4)                                   \
        {                                                              \
            const bool p0 = (tj) >= 0.25f;                             \
            const bool p1 = (tj) >= 0.375f;                            \
            const bool p2 = (tj) >= 0.5f;                              \
            const bool p3 = (tj) >= 0.625f;                            \
            cpk += (unsigned)p0 | ((unsigned)p1 << 8)                  \
                 | ((unsigned)p2 << 16) | ((unsigned)p3 << 24);        \
            if (p0) { A0 += (a0); B0 += (a1); }                        \
            if (p1) { A1 += (a1); B1 += (a2); }                        \
            if (p2) { A2 += (a2); B2 += (a3); }                        \
            if (p3) { A3 += (a3); B3 += (a4); }                        \
        }

        LANE(tv.x, x0.x, x1.x, x2.x, x3.x, x4.x);
        LANE(tv.y, x0.y, x1.y, x2.y, x3.y, x4.y);
        LANE(tv.z, x0.z, x1.z, x2.z, x3.z, x4.z);
        LANE(tv.w, x0.w, x1.w, x2.w, x3.w, x4.w);
#undef LANE
    }

    // ---- block reduction: warp shuffle -> shared -> global double atomics ----
    float vals[17] = { s0, s1, s2, s3, s4,
                       A0, A1, A2, A3,
                       B0, B1, B2, B3,
                       (float)( cpk        & 0xFF),
                       (float)((cpk >> 8)  & 0xFF),
                       (float)((cpk >> 16) & 0xFF),
                       (float)((cpk >> 24) & 0xFF) };
#pragma unroll
    for (int k = 0; k < 17; k++) {
#pragma unroll
        for (int o = 16; o > 0; o >>= 1)
            vals[k] += __shfl_down_sync(0xFFFFFFFFu, vals[k], o);
    }

    __shared__ float s_acc[17];
    if (threadIdx.x < 17) s_acc[threadIdx.x] = 0.f;
    __syncthreads();
    if ((threadIdx.x & 31) == 0) {
#pragma unroll
        for (int k = 0; k < 17; k++) atomicAdd(&s_acc[k], vals[k]);
    }
    __syncthreads();
    if (threadIdx.x < 17)
        atomicAdd(&g_acc[threadIdx.x], (double)s_acc[threadIdx.x]);
    __syncthreads();

    // ---- last-block finalize (fused; no extra kernel launches) ----
    if (threadIdx.x == 0) {
        __threadfence();
        const unsigned done = atomicAdd(&g_count, 1u);
        if (done == NBLKS - 1) {
            double v[17];
#pragma unroll
            for (int k = 0; k < 17; k++) v[k] = atomicAdd(&g_acc[k], 0.0);

            double cnt[5], inter[5];
            cnt[0] = npos - v[13];
            cnt[1] = v[13] - v[14];
            cnt[2] = v[14] - v[15];
            cnt[3] = v[15] - v[16];
            cnt[4] = v[16];
            inter[0] = v[0] - v[5];
            inter[1] = v[9] - v[6];
            inter[2] = v[10] - v[7];
            inter[3] = v[11] - v[8];
            inter[4] = v[12];

            const double S = 1e-5;
            double loss = 0.0;
#pragma unroll
            for (int c = 0; c < 5; c++) {
                const double dice = 1.0 - (2.0 * inter[c] + S) / (v[c] + cnt[c] + S);
                loss += (double)w[c] * dice;
            }
            out[0] = (float)loss;

            // restore state for the next (graph-replayed) call
#pragma unroll
            for (int k = 0; k < 17; k++) g_acc[k] = 0.0;
            __threadfence();
            g_count = 0;
        }
    }
}

extern "C" void kernel_launch(void* const* d_in, const int* in_sizes, int n_in,
                              void* d_out, int out_size)
{
    const float4* x = (const float4*)d_in[0];
    const float4* t = (const float4*)d_in[1];
    const float*  w = (const float*)d_in[2];
    float* out = (float*)d_out;

    dim3 grid(XB, NT);
    dice_fused<<<grid, NTHR>>>(x, t, w, out, (double)in_sizes[1]);
}